// round 2
// baseline (speedup 1.0000x reference)
#include <cuda_runtime.h>
#include <math.h>

#define B_SZ     128
#define L_Q      64
#define L_D      512
#define E_DIM    300
#define N_K      11
#define KT       50        // K-tile (300 = 6*50)
#define KSTEPS   6
#define NT       128       // docs per CTA chunk
#define NCHUNKS  4         // 512/128
#define NTHREADS 256

// cross-chunk pooling partials: [B][NCHUNKS][L_Q][N_K]  (written unconditionally)
__device__ float g_pool[B_SZ * NCHUNKS * L_Q * N_K];

// exp(-(CF)*(s-mu)^2) computed as 2^(-u^2) with u pre-scaled by sqrt(CF*log2e).
// Pure fma/alu path (no MUFU). Flushes to ~1e-38 below 2^-126 (harmless vs 1e-10 clip).
__device__ __forceinline__ float gauss2(float u) {
    float y = fmaxf(-u * u, -126.0f);
    float z = __fadd_rn(y, 12582912.0f);                 // 1.5*2^23: round-to-int in low bits
    float f = __fadd_rn(y, -__fadd_rn(z, -12582912.0f)); // frac in [-0.5, 0.5]
    float p =              1.3333558e-3f;                // 2^f Taylor (deg 5), err ~2e-6
    p = fmaf(p, f, 9.6181293e-3f);
    p = fmaf(p, f, 5.5504109e-2f);
    p = fmaf(p, f, 2.4022650e-1f);
    p = fmaf(p, f, 6.9314718e-1f);
    p = fmaf(p, f, 1.0f);
    int n = __float_as_int(z) - 0x4B400000;
    return p * __int_as_float((n + 127) << 23);          // p * 2^n
}

__global__ __launch_bounds__(NTHREADS, 2)
void knrm_main(const float* __restrict__ q,
               const float* __restrict__ d,
               const float* __restrict__ md)
{
    __shared__ float As[L_Q][KT];       // [m][k] broadcast reads
    __shared__ float Bs[KT][NT + 4];    // [k][n] padded, conflict-free float4
    __shared__ float s_invq[L_Q];
    __shared__ float s_invd[NT];
    __shared__ float s_maskd[NT];
    __shared__ float s_pool[L_Q][N_K];

    const int chunk = blockIdx.x;       // 0..3
    const int b     = blockIdx.y;       // 0..127
    const int n0    = chunk * NT;
    const int tid   = threadIdx.x;
    const int lane  = tid & 31;
    const int warp  = tid >> 5;
    const int tx    = tid & 15;
    const int ty    = tid >> 4;
    const int m0    = ty * 4;
    const int nn0   = tx * 8;

    const float* __restrict__ qb = q + (size_t)b * L_Q * E_DIM;
    const float* __restrict__ db = d + (size_t)b * L_D * E_DIM;

    // ---- inverse L2 norms: 64 q rows + this chunk's 128 d rows (warp per row) ----
    for (int r = warp; r < L_Q; r += 8) {
        float ss = 0.f;
        for (int k = lane; k < E_DIM; k += 32) { float v = qb[r * E_DIM + k]; ss = fmaf(v, v, ss); }
        #pragma unroll
        for (int o = 16; o > 0; o >>= 1) ss += __shfl_xor_sync(0xffffffffu, ss, o);
        if (lane == 0) s_invq[r] = 1.0f / fmaxf(sqrtf(ss), 1e-12f);
    }
    for (int r = warp; r < NT; r += 8) {
        float ss = 0.f;
        const float* row = db + (size_t)(n0 + r) * E_DIM;
        for (int k = lane; k < E_DIM; k += 32) { float v = row[k]; ss = fmaf(v, v, ss); }
        #pragma unroll
        for (int o = 16; o > 0; o >>= 1) ss += __shfl_xor_sync(0xffffffffu, ss, o);
        if (lane == 0) s_invd[r] = 1.0f / fmaxf(sqrtf(ss), 1e-12f);
    }
    for (int i = tid; i < NT; i += NTHREADS) s_maskd[i] = md[b * L_D + n0 + i];
    for (int i = tid; i < L_Q * N_K; i += NTHREADS) (&s_pool[0][0])[i] = 0.f;

    // ---- GEMM: 64 x 128 x 300, 4x8 micro-tile ----
    float acc[4][8];
    #pragma unroll
    for (int i = 0; i < 4; ++i)
        #pragma unroll
        for (int j = 0; j < 8; ++j) acc[i][j] = 0.f;

    for (int ks = 0; ks < KSTEPS; ++ks) {
        const int k0 = ks * KT;
        __syncthreads();
        for (int idx = tid; idx < L_Q * KT; idx += NTHREADS) {
            int r = idx / KT, kc = idx - r * KT;
            As[r][kc] = qb[r * E_DIM + k0 + kc];
        }
        for (int idx = tid; idx < NT * KT; idx += NTHREADS) {
            int r = idx / KT, kc = idx - r * KT;
            Bs[kc][r] = db[(size_t)(n0 + r) * E_DIM + k0 + kc];
        }
        __syncthreads();

        #pragma unroll 2
        for (int kt = 0; kt < KT; kt += 2) {
            float2 a[4];
            #pragma unroll
            for (int i = 0; i < 4; ++i) a[i] = *(const float2*)&As[m0 + i][kt];
            #pragma unroll
            for (int u = 0; u < 2; ++u) {
                const float4 b0 = *(const float4*)&Bs[kt + u][nn0];
                const float4 b1 = *(const float4*)&Bs[kt + u][nn0 + 4];
                #pragma unroll
                for (int i = 0; i < 4; ++i) {
                    const float av = u ? a[i].y : a[i].x;
                    acc[i][0] = fmaf(av, b0.x, acc[i][0]);
                    acc[i][1] = fmaf(av, b0.y, acc[i][1]);
                    acc[i][2] = fmaf(av, b0.z, acc[i][2]);
                    acc[i][3] = fmaf(av, b0.w, acc[i][3]);
                    acc[i][4] = fmaf(av, b1.x, acc[i][4]);
                    acc[i][5] = fmaf(av, b1.y, acc[i][5]);
                    acc[i][6] = fmaf(av, b1.z, acc[i][6]);
                    acc[i][7] = fmaf(av, b1.w, acc[i][7]);
                }
            }
        }
    }

    // ---- fused RBF pooling (all fma-pipe; u pre-scaled by sqrt(CF*log2e)) ----
    // C1 = sqrt(50*log2e), C0 = sqrt(5e5*log2e) = 100*C1
    const float C1 = 8.49321802f;
    const float C0 = 849.321802f;
    const float UC[N_K] = { C0 * 1.0f,
        C1 * 0.9f, C1 * 0.7f, C1 * 0.5f, C1 * 0.3f, C1 * 0.1f,
        C1 * -0.1f, C1 * -0.3f, C1 * -0.5f, C1 * -0.7f, C1 * -0.9f };

    float pool[4][N_K];
    #pragma unroll
    for (int i = 0; i < 4; ++i)
        #pragma unroll
        for (int k = 0; k < N_K; ++k) pool[i][k] = 0.f;

    float invd[8], mdv[8];
    #pragma unroll
    for (int j = 0; j < 8; ++j) { invd[j] = s_invd[nn0 + j]; mdv[j] = s_maskd[nn0 + j]; }

    #pragma unroll
    for (int i = 0; i < 4; ++i) {
        const float iq = s_invq[m0 + i];
        #pragma unroll
        for (int j = 0; j < 8; ++j) {
            const float s  = acc[i][j] * iq * invd[j];
            const float s0 = s * C0;
            const float s1 = s * C1;
            pool[i][0] = fmaf(mdv[j], gauss2(s0 - UC[0]), pool[i][0]);
            #pragma unroll
            for (int k = 1; k < N_K; ++k)
                pool[i][k] = fmaf(mdv[j], gauss2(s1 - UC[k]), pool[i][k]);
        }
    }

    __syncthreads();
    #pragma unroll
    for (int i = 0; i < 4; ++i)
        #pragma unroll
        for (int k = 0; k < N_K; ++k)
            atomicAdd(&s_pool[m0 + i][k], pool[i][k]);
    __syncthreads();

    // write chunk partials (unconditional -> no zeroing pass needed)
    float* gp = g_pool + ((size_t)(b * NCHUNKS + chunk) * L_Q) * N_K;
    for (int i = tid; i < L_Q * N_K; i += NTHREADS) gp[i] = (&s_pool[0][0])[i];
}

__global__ void knrm_finalize(const float* __restrict__ mq,
                              const float* __restrict__ w,
                              const float* __restrict__ bias,
                              float* __restrict__ out)
{
    __shared__ float s_red[L_Q];
    const int b = blockIdx.x;
    const int m = threadIdx.x;   // 64 threads

    const float* gp = g_pool + (size_t)b * NCHUNKS * L_Q * N_K;
    float ps[N_K];
    #pragma unroll
    for (int k = 0; k < N_K; ++k) ps[k] = 0.f;
    #pragma unroll
    for (int c = 0; c < NCHUNKS; ++c)
        #pragma unroll
        for (int k = 0; k < N_K; ++k)
            ps[k] += gp[(c * L_Q + m) * N_K + k];

    const float mqv = mq[b * L_Q + m] * 0.01f;
    float cm = 0.f;
    #pragma unroll
    for (int k = 0; k < N_K; ++k)
        cm = fmaf(logf(fmaxf(ps[k], 1e-10f)) * mqv, w[k], cm);
    s_red[m] = cm;
    __syncthreads();
    if (m == 0) {
        float s = bias[0];
        #pragma unroll
        for (int i = 0; i < L_Q; ++i) s += s_red[i];
        out[b] = tanhf(s);
    }
}

extern "C" void kernel_launch(void* const* d_in, const int* in_sizes, int n_in,
                              void* d_out, int out_size) {
    const float* q    = (const float*)d_in[0];   // [B, Lq, E]
    const float* d    = (const float*)d_in[1];   // [B, Ld, E]
    const float* mq   = (const float*)d_in[2];   // [B, Lq]
    const float* md   = (const float*)d_in[3];   // [B, Ld]
    const float* w    = (const float*)d_in[4];   // [1, K]
    const float* bias = (const float*)d_in[5];   // [1]
    float* out = (float*)d_out;                  // [B, 1]

    dim3 grid(NCHUNKS, B_SZ);
    knrm_main<<<grid, NTHREADS>>>(q, d, md);
    knrm_finalize<<<B_SZ, L_Q>>>(mq, w, bias, out);
}

// round 3
// speedup vs baseline: 1.5954x; 1.5954x over previous
#include <cuda_runtime.h>
#include <math.h>

#define B_SZ     128
#define L_Q      64
#define L_D      512
#define E_DIM    300
#define N_K      11
#define KT       30        // K-tile (300 = 10*30)
#define KSTEPS   10
#define NT       128       // docs per CTA chunk
#define NCHUNKS  4
#define NTHREADS 256

typedef unsigned long long u64;

// cross-chunk pooling partials [B][NCHUNKS][L_Q][N_K] + per-batch arrival tickets
__device__ float g_pool[B_SZ * NCHUNKS * L_Q * N_K];
__device__ unsigned int g_cnt[B_SZ];   // zero-init; last CTA resets -> graph-replay safe

__device__ __forceinline__ u64 pk2(float lo, float hi) {
    u64 r; asm("mov.b64 %0,{%1,%2};" : "=l"(r) : "f"(lo), "f"(hi)); return r;
}
__device__ __forceinline__ void upk2(float& lo, float& hi, u64 v) {
    asm("mov.b64 {%0,%1},%2;" : "=f"(lo), "=f"(hi) : "l"(v));
}
// packed dual-FMA: d += a*b  (fp32x2, SASS FFMA2 -> 2x fp32 throughput)
__device__ __forceinline__ void ffma2(u64& d, u64 a, u64 b) {
    asm("fma.rn.f32x2 %0,%1,%2,%0;" : "+l"(d) : "l"(a), "l"(b));
}
__device__ __forceinline__ float rcpa(float x) {
    float r; asm("rcp.approx.f32 %0,%1;" : "=f"(r) : "f"(x)); return r;
}
// 2^y, y in [-126, 15]; pure fma/alu (deg-5 poly, err ~2e-6)
__device__ __forceinline__ float exp2ff(float y) {
    float z = __fadd_rn(y, 12582912.0f);                 // 1.5*2^23 round trick
    float f = __fadd_rn(y, -__fadd_rn(z, -12582912.0f));
    float p =              1.3333558e-3f;
    p = fmaf(p, f, 9.6181293e-3f);
    p = fmaf(p, f, 5.5504109e-2f);
    p = fmaf(p, f, 2.4022650e-1f);
    p = fmaf(p, f, 6.9314718e-1f);
    p = fmaf(p, f, 1.0f);
    int n = __float_as_int(z) - 0x4B400000;
    return p * __int_as_float((n + 127) << 23);
}

__global__ __launch_bounds__(NTHREADS, 2)
void knrm_main(const float* __restrict__ q,
               const float* __restrict__ d,
               const float* __restrict__ mq,
               const float* __restrict__ md,
               const float* __restrict__ w,
               const float* __restrict__ bias,
               float* __restrict__ out)
{
    __shared__ __align__(16) u64   As2[L_Q][KT];      // q duplicated {a,a}
    __shared__ __align__(16) float Bs[KT][NT + 4];    // k-major docs
    __shared__ float s_invq[L_Q];
    __shared__ float s_invd[NT];
    __shared__ float s_maskd[NT];
    __shared__ float s_pool[L_Q * N_K];
    __shared__ float s_red[L_Q];
    __shared__ int   s_last;

    const int chunk = blockIdx.x;
    const int b     = blockIdx.y;
    const int n0    = chunk * NT;
    const int tid   = threadIdx.x;
    const int lane  = tid & 31;
    const int warp  = tid >> 5;
    const int tx    = tid & 15;
    const int ty    = tid >> 4;
    const int m0    = ty * 4;
    const int nA0   = tx * 4;        // low n-quad
    const int nB0   = 64 + tx * 4;   // high n-quad

    const float* __restrict__ qb = q + (size_t)b * L_Q * E_DIM;
    const float* __restrict__ db = d + (size_t)b * L_D * E_DIM;

    // ---- prologue: inverse L2 norms (warp per row) ----
    for (int r = warp; r < L_Q; r += 8) {
        float ss = 0.f;
        for (int k = lane; k < E_DIM; k += 32) { float v = qb[r * E_DIM + k]; ss = fmaf(v, v, ss); }
        #pragma unroll
        for (int o = 16; o > 0; o >>= 1) ss += __shfl_xor_sync(0xffffffffu, ss, o);
        if (lane == 0) s_invq[r] = 1.0f / fmaxf(sqrtf(ss), 1e-12f);
    }
    for (int r = warp; r < NT; r += 8) {
        float ss = 0.f;
        const float* row = db + (size_t)(n0 + r) * E_DIM;
        for (int k = lane; k < E_DIM; k += 32) { float v = row[k]; ss = fmaf(v, v, ss); }
        #pragma unroll
        for (int o = 16; o > 0; o >>= 1) ss += __shfl_xor_sync(0xffffffffu, ss, o);
        if (lane == 0) s_invd[r] = 1.0f / fmaxf(sqrtf(ss), 1e-12f);
    }
    for (int i = tid; i < NT; i += NTHREADS) s_maskd[i] = md[b * L_D + n0 + i];
    for (int i = tid; i < L_Q * N_K; i += NTHREADS) s_pool[i] = 0.f;

    // ---- GEMM 64x128x300, packed f32x2 (each FFMA2 = 2 MACs) ----
    u64 acc[4][4];
    #pragma unroll
    for (int i = 0; i < 4; ++i)
        #pragma unroll
        for (int p = 0; p < 4; ++p) acc[i][p] = 0ULL;

    for (int ks = 0; ks < KSTEPS; ++ks) {
        const int k0 = ks * KT;
        __syncthreads();
        for (int idx = tid; idx < L_Q * KT; idx += NTHREADS) {
            int r = idx / KT, kc = idx - r * KT;
            float v = qb[r * E_DIM + k0 + kc];
            As2[r][kc] = pk2(v, v);
        }
        for (int idx = tid; idx < NT * KT; idx += NTHREADS) {
            int r = idx / KT, kc = idx - r * KT;
            Bs[kc][r] = db[(size_t)(n0 + r) * E_DIM + k0 + kc];
        }
        __syncthreads();

        #pragma unroll 6
        for (int kt = 0; kt < KT; ++kt) {
            const ulonglong2 bL = *(const ulonglong2*)&Bs[kt][nA0];
            const ulonglong2 bH = *(const ulonglong2*)&Bs[kt][nB0];
            #pragma unroll
            for (int i = 0; i < 4; ++i) {
                const u64 a = As2[m0 + i][kt];
                ffma2(acc[i][0], a, bL.x);
                ffma2(acc[i][1], a, bL.y);
                ffma2(acc[i][2], a, bH.x);
                ffma2(acc[i][3], a, bH.y);
            }
        }
    }

    // ---- fused RBF pooling, factorized: exp(-50(s-mu)^2) = base * t^m * c ----
    float ivd[8], mdv[8];
    #pragma unroll
    for (int j = 0; j < 8; ++j) {
        const int ln = (j < 4) ? (nA0 + j) : (nB0 + j - 4);
        ivd[j] = s_invd[ln];
        mdv[j] = s_maskd[ln];
    }

    #pragma unroll
    for (int i = 0; i < 4; ++i) {
        const float iq = s_invq[m0 + i];
        float sj[8];
        upk2(sj[0], sj[1], acc[i][0]);
        upk2(sj[2], sj[3], acc[i][1]);
        upk2(sj[4], sj[5], acc[i][2]);
        upk2(sj[6], sj[7], acc[i][3]);

        float pl[N_K];
        #pragma unroll
        for (int k = 0; k < N_K; ++k) pl[k] = 0.f;

        #pragma unroll
        for (int j = 0; j < 8; ++j) {
            const float s  = sj[j] * iq * ivd[j];
            const float mv = mdv[j];
            const float s2 = s * s;
            const float base = exp2ff(fmaxf(s2 * -72.134752f, -126.f)); // e^{-50 s^2}
            const float t    = exp2ff(s * 14.4269504f);                 // e^{10 s}
            const float r    = rcpa(t);
            const float t2 = t * t, r2 = r * r;
            // all intermediates are exact kernel values (<=1): no overflow
            const float A1 = (base * t) * 0.60653066f;        // mu=0.1
            const float A3 = (A1 * t2) * 0.018315639f;        // mu=0.3
            const float A5 = (A3 * t2) * 3.3546263e-4f;       // mu=0.5
            const float A7 = (A5 * t2) * 6.1442124e-6f;       // mu=0.7
            const float A9 = (A7 * t2) * 1.1253517e-7f;       // mu=0.9
            const float B1 = (base * r) * 0.60653066f;        // mu=-0.1
            const float B3 = (B1 * r2) * 0.018315639f;
            const float B5 = (B3 * r2) * 3.3546263e-4f;
            const float B7 = (B5 * r2) * 6.1442124e-6f;
            const float B9 = (B7 * r2) * 1.1253517e-7f;
            pl[1]  = fmaf(mv, A9, pl[1]);
            pl[2]  = fmaf(mv, A7, pl[2]);
            pl[3]  = fmaf(mv, A5, pl[3]);
            pl[4]  = fmaf(mv, A3, pl[4]);
            pl[5]  = fmaf(mv, A1, pl[5]);
            pl[6]  = fmaf(mv, B1, pl[6]);
            pl[7]  = fmaf(mv, B3, pl[7]);
            pl[8]  = fmaf(mv, B5, pl[8]);
            pl[9]  = fmaf(mv, B7, pl[9]);
            pl[10] = fmaf(mv, B9, pl[10]);
            // kernel 0 (sigma=1e-3, mu=1): only non-negligible for |s-1|<0.0125
            const float d1 = s - 1.0f;
            if (fabsf(d1) < 0.0125f) {
                const float u = d1 * 849.321802f;
                pl[0] = fmaf(mv, exp2ff(fmaxf(-u * u, -126.f)), pl[0]);
            }
        }
        // half-warp (16 lanes share this m-range) shuffle-reduce, then smem atomic
        #pragma unroll
        for (int k = 0; k < N_K; ++k) {
            float v = pl[k];
            v += __shfl_xor_sync(0xffffffffu, v, 8);
            v += __shfl_xor_sync(0xffffffffu, v, 4);
            v += __shfl_xor_sync(0xffffffffu, v, 2);
            v += __shfl_xor_sync(0xffffffffu, v, 1);
            if ((lane & 15) == 0) atomicAdd(&s_pool[(m0 + i) * N_K + k], v);
        }
    }
    __syncthreads();

    // ---- publish chunk partials; last CTA of this batch finalizes ----
    float* gp = g_pool + (size_t)(b * NCHUNKS + chunk) * (L_Q * N_K);
    for (int i = tid; i < L_Q * N_K; i += NTHREADS) gp[i] = s_pool[i];
    __threadfence();
    __syncthreads();
    if (tid == 0) {
        unsigned int t = atomicAdd(&g_cnt[b], 1u);
        s_last = (t == NCHUNKS - 1);
    }
    __syncthreads();

    if (s_last) {
        __threadfence();
        const float* gb = g_pool + (size_t)b * NCHUNKS * L_Q * N_K;
        for (int i = tid; i < L_Q * N_K; i += NTHREADS)
            s_pool[i] = gb[i] + gb[L_Q * N_K + i] + gb[2 * L_Q * N_K + i] + gb[3 * L_Q * N_K + i];
        __syncthreads();
        if (tid < L_Q) {
            const float mqv = mq[b * L_Q + tid] * 0.01f;
            float cm = 0.f;
            #pragma unroll
            for (int k = 0; k < N_K; ++k)
                cm = fmaf(logf(fmaxf(s_pool[tid * N_K + k], 1e-10f)) * mqv, w[k], cm);
            s_red[tid] = cm;
        }
        __syncthreads();
        if (tid == 0) {
            float s = bias[0];
            #pragma unroll
            for (int m = 0; m < L_Q; ++m) s += s_red[m];
            out[b] = tanhf(s);
            g_cnt[b] = 0;   // reset for next graph replay
        }
    }
}

extern "C" void kernel_launch(void* const* d_in, const int* in_sizes, int n_in,
                              void* d_out, int out_size) {
    const float* q    = (const float*)d_in[0];   // [B, Lq, E]
    const float* d    = (const float*)d_in[1];   // [B, Ld, E]
    const float* mq   = (const float*)d_in[2];   // [B, Lq]
    const float* md   = (const float*)d_in[3];   // [B, Ld]
    const float* w    = (const float*)d_in[4];   // [1, K]
    const float* bias = (const float*)d_in[5];   // [1]
    float* out = (float*)d_out;                  // [B, 1]

    dim3 grid(NCHUNKS, B_SZ);
    knrm_main<<<grid, NTHREADS>>>(q, d, mq, md, w, bias, out);
}

// round 5
// speedup vs baseline: 2.3812x; 1.4926x over previous
#include <cuda_runtime.h>
#include <cuda_bf16.h>
#include <math.h>
#include <stdint.h>

#define B_SZ     128
#define L_Q      64
#define L_D      512
#define E_DIM    300
#define N_K      11
#define NT       128        // docs per CTA chunk
#define NCHUNKS  4
#define NTHREADS 256
#define KC       64         // k-cols per chunk tile
#define CKN      5          // 5*64 = 320 >= 300
#define LDA      72         // smem row stride in bf16 (+8 pad -> conflict-free ldmatrix)

// ---- dynamic smem layout (bytes) ----
#define OFF_AHI   0                       // 64 x 72 bf16
#define OFF_ALO   9216
#define OFF_BHI   18432                   // 128 x 72 bf16
#define OFF_BLO   36864
#define OFF_INVQ  55296                   // 64 f32
#define OFF_INVD  (OFF_INVQ + 256)       // 128 f32
#define OFF_MASKD (OFF_INVD + 512)       // 128 f32
#define OFF_POOL  (OFF_MASKD + 512)      // 64*11 f32
#define OFF_RED   (OFF_POOL + 2816)      // 64 f32
#define SMEM_TOTAL (OFF_RED + 256)       // 59904 B

__device__ float g_pool[B_SZ * NCHUNKS * L_Q * N_K];
__device__ unsigned int g_cnt[B_SZ];   // zero-init; last CTA resets (graph-replay safe)

__device__ __forceinline__ uint32_t smem_u32(const void* p) {
    uint32_t a;
    asm("{ .reg .u64 t; cvta.to.shared.u64 t, %1; cvt.u32.u64 %0, t; }" : "=r"(a) : "l"(p));
    return a;
}
__device__ __forceinline__ void ldm_x4(uint32_t* r, uint32_t addr) {
    asm volatile("ldmatrix.sync.aligned.m8n8.x4.shared.b16 {%0,%1,%2,%3}, [%4];"
        : "=r"(r[0]), "=r"(r[1]), "=r"(r[2]), "=r"(r[3]) : "r"(addr));
}
__device__ __forceinline__ void mma16816(float* c, const uint32_t* a, uint32_t b0, uint32_t b1) {
    asm volatile("mma.sync.aligned.m16n8k16.row.col.f32.bf16.bf16.f32 "
        "{%0,%1,%2,%3},{%4,%5,%6,%7},{%8,%9},{%0,%1,%2,%3};"
        : "+f"(c[0]), "+f"(c[1]), "+f"(c[2]), "+f"(c[3])
        : "r"(a[0]), "r"(a[1]), "r"(a[2]), "r"(a[3]), "r"(b0), "r"(b1));
}
__device__ __forceinline__ float rcpa(float x) {
    float r; asm("rcp.approx.f32 %0,%1;" : "=f"(r) : "f"(x)); return r;
}
// 2^y for y in [-126, 15], pure fma/alu, err ~2e-6
__device__ __forceinline__ float exp2ff(float y) {
    float z = __fadd_rn(y, 12582912.0f);
    float f = __fadd_rn(y, -__fadd_rn(z, -12582912.0f));
    float p =              1.3333558e-3f;
    p = fmaf(p, f, 9.6181293e-3f);
    p = fmaf(p, f, 5.5504109e-2f);
    p = fmaf(p, f, 2.4022650e-1f);
    p = fmaf(p, f, 6.9314718e-1f);
    p = fmaf(p, f, 1.0f);
    int n = __float_as_int(z) - 0x4B400000;
    return p * __int_as_float((n + 127) << 23);
}

// convert/split one 8-element unit of a row into hi/lo bf16 smem tiles (linear layout)
__device__ __forceinline__ void write_unit(char* sm, int baseHI, int baseLO,
                                           int row, int unit,
                                           const float* __restrict__ gp,
                                           int kbase, float inv) {
    __nv_bfloat16 hb[8], lb[8];
    #pragma unroll
    for (int e = 0; e < 8; ++e) {
        const int k = kbase + unit * 8 + e;
        const float x = (k < E_DIM) ? gp[k] * inv : 0.f;
        const __nv_bfloat16 h = __float2bfloat16(x);
        hb[e] = h;
        lb[e] = __float2bfloat16(x - __bfloat162float(h));
    }
    const uint32_t off = ((uint32_t)row * LDA + (uint32_t)unit * 8) * 2;
    *(uint4*)(sm + baseHI + off) = *(const uint4*)hb;
    *(uint4*)(sm + baseLO + off) = *(const uint4*)lb;
}

__global__ __launch_bounds__(NTHREADS, 2)
void knrm_hmma(const float* __restrict__ q,
               const float* __restrict__ d,
               const float* __restrict__ mq,
               const float* __restrict__ md,
               const float* __restrict__ w,
               const float* __restrict__ bias,
               float* __restrict__ out)
{
    extern __shared__ char sm[];
    const uint32_t smb = smem_u32(sm);
    const int chunk = blockIdx.x;
    const int b     = blockIdx.y;
    const int n0g   = chunk * NT;
    const int tid   = threadIdx.x;
    const int lane  = tid & 31;
    const int warp  = tid >> 5;
    const int wm    = warp >> 2;     // 0..1 : query rows wm*32
    const int wn    = warp & 3;      // 0..3 : doc cols  wn*32

    float* s_invq  = (float*)(sm + OFF_INVQ);
    float* s_invd  = (float*)(sm + OFF_INVD);
    float* s_maskd = (float*)(sm + OFF_MASKD);
    float* s_pool  = (float*)(sm + OFF_POOL);
    float* s_red   = (float*)(sm + OFF_RED);

    const float* __restrict__ qb = q + (size_t)b * L_Q * E_DIM;
    const float* __restrict__ db = d + (size_t)b * L_D * E_DIM;

    // ---- prologue: inverse L2 norms (warp per row) ----
    for (int r = warp; r < L_Q; r += 8) {
        float ss = 0.f;
        for (int k = lane; k < E_DIM; k += 32) { float v = qb[r * E_DIM + k]; ss = fmaf(v, v, ss); }
        #pragma unroll
        for (int o = 16; o > 0; o >>= 1) ss += __shfl_xor_sync(0xffffffffu, ss, o);
        if (lane == 0) s_invq[r] = 1.0f / fmaxf(sqrtf(ss), 1e-12f);
    }
    for (int r = warp; r < NT; r += 8) {
        float ss = 0.f;
        const float* row = db + (size_t)(n0g + r) * E_DIM;
        for (int k = lane; k < E_DIM; k += 32) { float v = row[k]; ss = fmaf(v, v, ss); }
        #pragma unroll
        for (int o = 16; o > 0; o >>= 1) ss += __shfl_xor_sync(0xffffffffu, ss, o);
        if (lane == 0) s_invd[r] = 1.0f / fmaxf(sqrtf(ss), 1e-12f);
    }
    for (int i = tid; i < NT; i += NTHREADS) s_maskd[i] = md[b * L_D + n0g + i];
    for (int i = tid; i < L_Q * N_K; i += NTHREADS) s_pool[i] = 0.f;

    // ---- GEMM: 64q x 128d x 320k, bf16 hi/lo 3-pass HMMA ----
    float acc[2][4][4];
    #pragma unroll
    for (int mt = 0; mt < 2; ++mt)
        #pragma unroll
        for (int nt = 0; nt < 4; ++nt)
            #pragma unroll
            for (int c = 0; c < 4; ++c) acc[mt][nt][c] = 0.f;

    const int arow = lane & 15;
    const int acol = (lane >> 4) << 3;

    for (int ck = 0; ck < CKN; ++ck) {
        const int kbase = ck * KC;
        __syncthreads();
        // convert: queries 64x8 units, docs 128x8 units
        for (int idx = tid; idx < (L_Q + NT) * 8; idx += NTHREADS) {
            if (idx < L_Q * 8) {
                const int row = idx >> 3, u = idx & 7;
                write_unit(sm, OFF_AHI, OFF_ALO, row, u,
                           qb + (size_t)row * E_DIM, kbase, s_invq[row]);
            } else {
                const int i2 = idx - L_Q * 8;
                const int row = i2 >> 3, u = i2 & 7;
                write_unit(sm, OFF_BHI, OFF_BLO, row, u,
                           db + (size_t)(n0g + row) * E_DIM, kbase, s_invd[row]);
            }
        }
        __syncthreads();

        #pragma unroll
        for (int ks = 0; ks < 4; ++ks) {
            const int kk = ks * 16;
            uint32_t ah[2][4], al[2][4], bh[2][4], bl[2][4];
            #pragma unroll
            for (int mt = 0; mt < 2; ++mt) {
                const uint32_t aoff = ((uint32_t)(wm * 32 + mt * 16 + arow) * LDA + kk + acol) * 2;
                ldm_x4(ah[mt], smb + OFF_AHI + aoff);
                ldm_x4(al[mt], smb + OFF_ALO + aoff);
            }
            #pragma unroll
            for (int np = 0; np < 2; ++np) {
                const uint32_t boff = ((uint32_t)(wn * 32 + np * 16 + arow) * LDA + kk + acol) * 2;
                ldm_x4(bh[np], smb + OFF_BHI + boff);
                ldm_x4(bl[np], smb + OFF_BLO + boff);
            }
            #pragma unroll
            for (int mt = 0; mt < 2; ++mt)
                #pragma unroll
                for (int nt = 0; nt < 4; ++nt) {
                    const int np = nt >> 1, sl = nt & 1;
                    mma16816(acc[mt][nt], ah[mt], bh[np][sl], bh[np][sl + 2]);
                    mma16816(acc[mt][nt], ah[mt], bl[np][sl], bl[np][sl + 2]);
                    mma16816(acc[mt][nt], al[mt], bh[np][sl], bh[np][sl + 2]);
                }
        }
    }
    __syncthreads();

    // ---- pooling straight from accumulator fragments ----
    #pragma unroll
    for (int mt = 0; mt < 2; ++mt) {
        #pragma unroll
        for (int rh = 0; rh < 2; ++rh) {
            const int row = wm * 32 + mt * 16 + (lane >> 2) + rh * 8;   // query index
            float pl[N_K];
            #pragma unroll
            for (int k = 0; k < N_K; ++k) pl[k] = 0.f;
            #pragma unroll
            for (int nt = 0; nt < 4; ++nt) {
                #pragma unroll
                for (int cm = 0; cm < 2; ++cm) {
                    const int nl = wn * 32 + nt * 8 + (lane & 3) * 2 + cm;  // local doc
                    const float s  = acc[mt][nt][rh * 2 + cm];
                    const float mv = s_maskd[nl];
                    const float base = exp2ff(fmaxf(s * s * -72.134752f, -126.f)); // e^{-50 s^2}
                    const float t    = exp2ff(s * 14.4269504f);                    // e^{10 s}
                    const float r    = rcpa(t);
                    const float t2 = t * t, r2 = r * r;
                    const float A1 = (base * t) * 0.60653066f;
                    const float A3 = (A1 * t2) * 0.018315639f;
                    const float A5 = (A3 * t2) * 3.3546263e-4f;
                    const float A7 = (A5 * t2) * 6.1442124e-6f;
                    const float A9 = (A7 * t2) * 1.1253517e-7f;
                    const float B1 = (base * r) * 0.60653066f;
                    const float B3 = (B1 * r2) * 0.018315639f;
                    const float B5 = (B3 * r2) * 3.3546263e-4f;
                    const float B7 = (B5 * r2) * 6.1442124e-6f;
                    const float B9 = (B7 * r2) * 1.1253517e-7f;
                    pl[1]  = fmaf(mv, A9, pl[1]);
                    pl[2]  = fmaf(mv, A7, pl[2]);
                    pl[3]  = fmaf(mv, A5, pl[3]);
                    pl[4]  = fmaf(mv, A3, pl[4]);
                    pl[5]  = fmaf(mv, A1, pl[5]);
                    pl[6]  = fmaf(mv, B1, pl[6]);
                    pl[7]  = fmaf(mv, B3, pl[7]);
                    pl[8]  = fmaf(mv, B5, pl[8]);
                    pl[9]  = fmaf(mv, B7, pl[9]);
                    pl[10] = fmaf(mv, B9, pl[10]);
                    const float d1 = s - 1.0f;   // kernel 0: sigma=1e-3
                    if (fabsf(d1) < 0.0125f) {
                        const float u = d1 * 849.321802f;
                        pl[0] = fmaf(mv, exp2ff(fmaxf(-u * u, -126.f)), pl[0]);
                    }
                }
            }
            #pragma unroll
            for (int k = 0; k < N_K; ++k) {
                float v = pl[k];
                v += __shfl_xor_sync(0xffffffffu, v, 1);
                v += __shfl_xor_sync(0xffffffffu, v, 2);
                if ((lane & 3) == 0) atomicAdd(&s_pool[row * N_K + k], v);
            }
        }
    }
    __syncthreads();

    // ---- publish chunk partials; last CTA of this batch finalizes ----
    float* gp = g_pool + (size_t)(b * NCHUNKS + chunk) * (L_Q * N_K);
    for (int i = tid; i < L_Q * N_K; i += NTHREADS) gp[i] = s_pool[i];
    __threadfence();
    __syncthreads();
    __shared__ int s_last;
    if (tid == 0) {
        unsigned int t = atomicAdd(&g_cnt[b], 1u);
        s_last = (t == NCHUNKS - 1);
    }
    __syncthreads();

    if (s_last) {
        __threadfence();
        const float* gb = g_pool + (size_t)b * NCHUNKS * L_Q * N_K;
        for (int i = tid; i < L_Q * N_K; i += NTHREADS)
            s_pool[i] = gb[i] + gb[L_Q * N_K + i] + gb[2 * L_Q * N_K + i] + gb[3 * L_Q * N_K + i];
        __syncthreads();
        if (tid < L_Q) {
            const float mqv = mq[b * L_Q + tid] * 0.01f;
            float cm = 0.f;
            #pragma unroll
            for (int k = 0; k < N_K; ++k)
                cm = fmaf(logf(fmaxf(s_pool[tid * N_K + k], 1e-10f)) * mqv, w[k], cm);
            s_red[tid] = cm;
        }
        __syncthreads();
        if (tid == 0) {
            float s = bias[0];
            #pragma unroll
            for (int m = 0; m < L_Q; ++m) s += s_red[m];
            out[b] = tanhf(s);
            g_cnt[b] = 0;   // reset for next graph replay
        }
    }
}

extern "C" void kernel_launch(void* const* d_in, const int* in_sizes, int n_in,
                              void* d_out, int out_size) {
    const float* q    = (const float*)d_in[0];   // [B, Lq, E]
    const float* d    = (const float*)d_in[1];   // [B, Ld, E]
    const float* mq   = (const float*)d_in[2];   // [B, Lq]
    const float* md   = (const float*)d_in[3];   // [B, Ld]
    const float* w    = (const float*)d_in[4];   // [1, K]
    const float* bias = (const float*)d_in[5];   // [1]
    float* out = (float*)d_out;                  // [B, 1]

    cudaFuncSetAttribute(knrm_hmma, cudaFuncAttributeMaxDynamicSharedMemorySize, SMEM_TOTAL);
    dim3 grid(NCHUNKS, B_SZ);
    knrm_hmma<<<grid, NTHREADS, SMEM_TOTAL>>>(q, d, mq, md, w, bias, out);
}